// round 13
// baseline (speedup 1.0000x reference)
#include <cuda_runtime.h>
#include <mma.h>
#include <math.h>
#include <stdint.h>

using namespace nvcuda;

#define B_SZ 4
#define T_SZ 2048
#define C_SZ 1024
#define H_SZ 16
#define D_SZ 64
#define M_SZ (B_SZ * T_SZ)   // 8192

// ---------------- scratch (static device globals; no allocation) ----------------
__device__ float g_q[(size_t)B_SZ * H_SZ * T_SZ * D_SZ];   // [B,H,T,D] tf32-rounded
__device__ float g_k[(size_t)B_SZ * H_SZ * T_SZ * D_SZ];
__device__ float g_v[(size_t)B_SZ * H_SZ * T_SZ * D_SZ];
__device__ float g_ao[(size_t)B_SZ * T_SZ * C_SZ];         // attention out, tf32-rounded
__device__ float g_xr[(size_t)M_SZ * C_SZ];                // x, tf32-rounded
__device__ float g_wqkv[(size_t)C_SZ * 3 * C_SZ];          // W_qkv, tf32-rounded
__device__ float g_wout[(size_t)C_SZ * C_SZ];              // W_out, tf32-rounded

// ---------------- cp.async helpers ----------------
__device__ __forceinline__ void cp_async16(void* smem, const void* gmem) {
    uint32_t s = (uint32_t)__cvta_generic_to_shared(smem);
    asm volatile("cp.async.cg.shared.global [%0], [%1], 16;\n" :: "r"(s), "l"(gmem));
}
__device__ __forceinline__ void cp_commit() {
    asm volatile("cp.async.commit_group;\n");
}
template<int N>
__device__ __forceinline__ void cp_wait() {
    asm volatile("cp.async.wait_group %0;\n" :: "n"(N));
}

// ---------------- raw tf32 mma (PTX-defined fragment layout) ----------------
__device__ __forceinline__ void mma_tf32(float* c, const uint32_t* a, const uint32_t* b) {
    asm volatile(
        "mma.sync.aligned.m16n8k8.row.col.f32.tf32.tf32.f32 "
        "{%0,%1,%2,%3}, {%4,%5,%6,%7}, {%8,%9}, {%0,%1,%2,%3};\n"
        : "+f"(c[0]), "+f"(c[1]), "+f"(c[2]), "+f"(c[3])
        : "r"(a[0]), "r"(a[1]), "r"(a[2]), "r"(a[3]), "r"(b[0]), "r"(b[1]));
}

// ---------------- prep: round all three operand arrays to tf32 (one launch) -----
#define XR_F4   (M_SZ * C_SZ / 4)            // 2,097,152
#define WQKV_F4 (3 * C_SZ * C_SZ / 4)        //   786,432
#define WOUT_F4 (C_SZ * C_SZ / 4)            //   262,144
#define PREP_F4 (XR_F4 + WQKV_F4 + WOUT_F4)  // 3,145,728

__global__ void round_all(const float4* __restrict__ x,
                          const float4* __restrict__ wqkv,
                          const float4* __restrict__ wout)
{
    int i = blockIdx.x * blockDim.x + threadIdx.x;
    if (i >= PREP_F4) return;
    const float4* src;
    float4* dst;
    if (i < XR_F4) {
        src = x + i;                     dst = (float4*)g_xr + i;
    } else if (i < XR_F4 + WQKV_F4) {
        int j = i - XR_F4;
        src = wqkv + j;                  dst = (float4*)g_wqkv + j;
    } else {
        int j = i - XR_F4 - WQKV_F4;
        src = wout + j;                  dst = (float4*)g_wout + j;
    }
    float4 v = *src;
    v.x = wmma::__float_to_tf32(v.x);
    v.y = wmma::__float_to_tf32(v.y);
    v.z = wmma::__float_to_tf32(v.z);
    v.w = wmma::__float_to_tf32(v.w);
    *dst = v;
}

// ---------------- GEMM v3b: raw m16n8k8 mma, 128x128 CTA, GS=2, 3 CTAs/SM -------
// (unchanged from R12)
#define BM 128
#define BN 128
#define BK 32
#define GS 2
#define LDA (BK + 4)    // 36
#define LDB (BN + 4)    // 132
#define A_STG (BM * LDA)          // 4608 floats
#define B_STG (BK * LDB)          // 4224 floats
#define GEMM_SMEM_BYTES (GS * (A_STG + B_STG) * 4)   // 70656 B -> 3 CTAs/SM

__global__ void __launch_bounds__(128, 3) gemm_tf32(
    const float* __restrict__ bias, float* __restrict__ Cout,
    int M, int N, int K, int mode)
{
    extern __shared__ float gsm[];
    float* Ash = gsm;
    float* Bsh = gsm + GS * A_STG;

    const float* Aptr = (mode == 1) ? g_ao : g_xr;
    const float* Bm   = (mode == 1) ? g_wout : g_wqkv;

    int tid  = threadIdx.x;
    int warp = tid >> 5;
    int lane = tid & 31;
    int wm = warp >> 1;
    int wn = warp & 1;
    int g  = lane >> 2;
    int t  = lane & 3;
    int m0 = blockIdx.y * BM;
    int n0 = blockIdx.x * BN;

    float acc[4][8][4];
    #pragma unroll
    for (int i = 0; i < 4; i++)
        #pragma unroll
        for (int f = 0; f < 8; f++)
            #pragma unroll
            for (int e = 0; e < 4; e++) acc[i][f][e] = 0.f;

    int ar = tid >> 3,  ac = (tid & 7)  * 4;
    int br = tid >> 5,  bc = (tid & 31) * 4;

    auto load_tile = [&](int stage, int k0) {
        float* As = Ash + stage * A_STG;
        float* Bs = Bsh + stage * B_STG;
        #pragma unroll
        for (int i = 0; i < 8; i++) {
            int r = ar + i * 16;
            cp_async16(As + r * LDA + ac, Aptr + (size_t)(m0 + r) * K + k0 + ac);
        }
        #pragma unroll
        for (int i = 0; i < 8; i++) {
            int r = br + i * 4;
            cp_async16(Bs + r * LDB + bc, Bm + (size_t)(k0 + r) * N + n0 + bc);
        }
        cp_commit();
    };

    int KT = K / BK;
    load_tile(0, 0);

    for (int kt = 0; kt < KT; ++kt) {
        __syncthreads();
        if (kt + 1 < KT) {
            load_tile((kt + 1) & 1, (kt + 1) * BK);
            cp_wait<1>();
        } else {
            cp_wait<0>();
        }
        __syncthreads();

        float* As = Ash + (kt & 1) * A_STG;
        float* Bs = Bsh + (kt & 1) * B_STG;

        #pragma unroll
        for (int kk = 0; kk < BK; kk += 8) {
            uint32_t a[4][4];
            #pragma unroll
            for (int i = 0; i < 4; i++) {
                int rA = wm * 64 + i * 16 + g;
                a[i][0] = __float_as_uint(As[(rA    ) * LDA + kk + t]);
                a[i][1] = __float_as_uint(As[(rA + 8) * LDA + kk + t]);
                a[i][2] = __float_as_uint(As[(rA    ) * LDA + kk + t + 4]);
                a[i][3] = __float_as_uint(As[(rA + 8) * LDA + kk + t + 4]);
            }
            #pragma unroll
            for (int f = 0; f < 8; f++) {
                uint32_t bb[2];
                int nB = wn * 64 + f * 8 + g;
                bb[0] = __float_as_uint(Bs[(kk + t)     * LDB + nB]);
                bb[1] = __float_as_uint(Bs[(kk + t + 4) * LDB + nB]);
                #pragma unroll
                for (int i = 0; i < 4; i++)
                    mma_tf32(acc[i][f], a[i], bb);
            }
        }
    }
    __syncthreads();

    float* stg = Ash + warp * 1152;
    #pragma unroll
    for (int i = 0; i < 4; i++) {
        #pragma unroll
        for (int f = 0; f < 8; f++) {
            *(float2*)(stg + (g    ) * 68 + f * 8 + 2 * t) = make_float2(acc[i][f][0], acc[i][f][1]);
            *(float2*)(stg + (g + 8) * 68 + f * 8 + 2 * t) = make_float2(acc[i][f][2], acc[i][f][3]);
        }
        __syncwarp();
        #pragma unroll
        for (int e = 0; e < 8; e++) {
            int idx = lane + e * 32;
            int rr = idx >> 4, cc = (idx & 15) * 4;
            int m = m0 + wm * 64 + i * 16 + rr;
            int n = n0 + wn * 64 + cc;
            float4 v  = *(float4*)(stg + rr * 68 + cc);
            float4 bv = *(const float4*)(bias + n);
            v.x += bv.x; v.y += bv.y; v.z += bv.z; v.w += bv.w;
            if (mode == 0) {
                int third = n >> 10, c = n & 1023;
                int h = c >> 6, d = c & 63;
                int b = m >> 11, tt = m & 2047;
                float* dst = (third == 0) ? g_q : (third == 1) ? g_k : g_v;
                v.x = wmma::__float_to_tf32(v.x);
                v.y = wmma::__float_to_tf32(v.y);
                v.z = wmma::__float_to_tf32(v.z);
                v.w = wmma::__float_to_tf32(v.w);
                *(float4*)(dst + (((size_t)(b * H_SZ + h)) * T_SZ + tt) * D_SZ + d) = v;
            } else {
                *(float4*)(Cout + (size_t)m * N + n) = v;
            }
        }
        __syncwarp();
    }
}

// ---------------- Flash attention v2: shfl P-transpose, no Ssh, 3 CTAs/SM --------
// One CTA per (b,h,128-row Q tile). 8 warps x 16 rows. S and P never touch smem:
// the C-frag -> A-frag relayout is an intra-quad shuffle. O normalized in regs.
#define AQ 128
#define AK 64
#define ALD 68
#define ATT_SMEM_FLOATS (AQ * ALD + AK * ALD + AK * ALD)
#define ATT_SMEM_BYTES  (ATT_SMEM_FLOATS * 4)   // 69632 B -> 3 CTAs/SM

__global__ void __launch_bounds__(256, 3) attn_kernel()
{
    extern __shared__ float smbuf[];
    float* Qsh = smbuf;
    float* Ksh = Qsh + AQ * ALD;
    float* Vsh = Ksh + AK * ALD;

    int qt = gridDim.x - 1 - blockIdx.x;   // longest tiles first
    int q0 = qt * AQ;
    int bh = blockIdx.y;
    int b = bh >> 4, h = bh & 15;

    const float* Qb = g_q + (size_t)bh * T_SZ * D_SZ;
    const float* Kb = g_k + (size_t)bh * T_SZ * D_SZ;
    const float* Vb = g_v + (size_t)bh * T_SZ * D_SZ;

    int tid  = threadIdx.x;
    int warp = tid >> 5;
    int lane = tid & 31;
    int r0 = warp * 16;
    int g = lane >> 2;
    int t = lane & 3;
    int rowA = r0 + g, rowB = rowA + 8;
    int qiA = q0 + rowA, qiB = q0 + rowB;

    // load Q tile with 0.125 scale folded in
    #pragma unroll
    for (int i = 0; i < 8; i++) {
        int idx = tid + i * 256;
        int r = idx >> 4, c = (idx & 15) * 4;
        float4 v = *(const float4*)(Qb + (size_t)(q0 + r) * D_SZ + c);
        v.x *= 0.125f; v.y *= 0.125f; v.z *= 0.125f; v.w *= 0.125f;
        *(float4*)(Qsh + r * ALD + c) = v;
    }

    float oacc[8][4];
    #pragma unroll
    for (int f = 0; f < 8; f++)
        #pragma unroll
        for (int e = 0; e < 4; e++) oacc[f][e] = 0.f;

    float laccA = 0.f, laccB = 0.f;

    int kr = tid >> 4, kc = (tid & 15) * 4;
    int nkt = 2 * qt + 2;

    int srcA = (lane & 0x1C) | (t >> 1);   // 4g + t/2
    int srcB = srcA + 2;
    bool odd = (t & 1);

    for (int kt = 0; kt < nkt; ++kt) {
        int k0 = kt * AK;
        __syncthreads();
        #pragma unroll
        for (int i = 0; i < 4; i++) {
            int r = kr + i * 16;
            cp_async16(Ksh + r * ALD + kc, Kb + (size_t)(k0 + r) * D_SZ + kc);
            cp_async16(Vsh + r * ALD + kc, Vb + (size_t)(k0 + r) * D_SZ + kc);
        }
        cp_commit();
        cp_wait<0>();
        __syncthreads();

        // ---- S = (Q*0.125) @ K^T, in registers ----
        float sacc[8][4];
        #pragma unroll
        for (int f = 0; f < 8; f++)
            #pragma unroll
            for (int e = 0; e < 4; e++) sacc[f][e] = 0.f;

        #pragma unroll
        for (int kk = 0; kk < 64; kk += 8) {
            uint32_t a[4];
            a[0] = __float_as_uint(Qsh[rowA * ALD + kk + t]);
            a[1] = __float_as_uint(Qsh[rowB * ALD + kk + t]);
            a[2] = __float_as_uint(Qsh[rowA * ALD + kk + t + 4]);
            a[3] = __float_as_uint(Qsh[rowB * ALD + kk + t + 4]);
            #pragma unroll
            for (int f = 0; f < 8; f++) {
                uint32_t bb[2];
                bb[0] = __float_as_uint(Ksh[(f * 8 + g) * ALD + kk + t]);
                bb[1] = __float_as_uint(Ksh[(f * 8 + g) * ALD + kk + t + 4]);
                mma_tf32(sacc[f], a, bb);
            }
        }

        // ---- softmax numerator in registers ----
        #pragma unroll
        for (int f = 0; f < 8; f++) {
            int c0 = k0 + f * 8 + 2 * t;
            float p0 = (c0     <= qiA) ? __expf(fminf(sacc[f][0], 60.f)) : 0.f;
            float p1 = (c0 + 1 <= qiA) ? __expf(fminf(sacc[f][1], 60.f)) : 0.f;
            float p2 = (c0     <= qiB) ? __expf(fminf(sacc[f][2], 60.f)) : 0.f;
            float p3 = (c0 + 1 <= qiB) ? __expf(fminf(sacc[f][3], 60.f)) : 0.f;
            p0 = wmma::__float_to_tf32(p0);
            p1 = wmma::__float_to_tf32(p1);
            p2 = wmma::__float_to_tf32(p2);
            p3 = wmma::__float_to_tf32(p3);
            laccA += p0 + p1;
            laccB += p2 + p3;
            sacc[f][0] = p0; sacc[f][1] = p1; sacc[f][2] = p2; sacc[f][3] = p3;
        }

        // ---- O += P @ V; P relayout C-frag -> A-frag via quad shuffles ----
        #pragma unroll
        for (int fk = 0; fk < 8; fk++) {
            float x0 = __shfl_sync(0xffffffffu, sacc[fk][0], srcA);
            float x1 = __shfl_sync(0xffffffffu, sacc[fk][1], srcA);
            float y0 = __shfl_sync(0xffffffffu, sacc[fk][2], srcA);
            float y1 = __shfl_sync(0xffffffffu, sacc[fk][3], srcA);
            float z0 = __shfl_sync(0xffffffffu, sacc[fk][0], srcB);
            float z1 = __shfl_sync(0xffffffffu, sacc[fk][1], srcB);
            float w0 = __shfl_sync(0xffffffffu, sacc[fk][2], srcB);
            float w1 = __shfl_sync(0xffffffffu, sacc[fk][3], srcB);
            uint32_t a[4];
            a[0] = __float_as_uint(odd ? x1 : x0);   // P[rowA][8fk + t]
            a[1] = __float_as_uint(odd ? y1 : y0);   // P[rowB][8fk + t]
            a[2] = __float_as_uint(odd ? z1 : z0);   // P[rowA][8fk + t+4]
            a[3] = __float_as_uint(odd ? w1 : w0);   // P[rowB][8fk + t+4]
            int kk = fk * 8;
            #pragma unroll
            for (int f = 0; f < 8; f++) {
                uint32_t bb[2];
                bb[0] = __float_as_uint(Vsh[(kk + t)     * ALD + f * 8 + g]);
                bb[1] = __float_as_uint(Vsh[(kk + t + 4) * ALD + f * 8 + g]);
                mma_tf32(oacc[f], a, bb);
            }
        }
    }

    // ---- row-sum reduction across the quad, normalize O, write directly ----
    laccA += __shfl_xor_sync(0xffffffffu, laccA, 1);
    laccA += __shfl_xor_sync(0xffffffffu, laccA, 2);
    laccB += __shfl_xor_sync(0xffffffffu, laccB, 1);
    laccB += __shfl_xor_sync(0xffffffffu, laccB, 2);
    float invA = 1.0f / laccA;
    float invB = 1.0f / laccB;

    float* aoA = g_ao + (size_t)(b * T_SZ + q0 + rowA) * C_SZ + h * D_SZ + 2 * t;
    float* aoB = g_ao + (size_t)(b * T_SZ + q0 + rowB) * C_SZ + h * D_SZ + 2 * t;
    #pragma unroll
    for (int f = 0; f < 8; f++) {
        float2 vA, vB;
        vA.x = wmma::__float_to_tf32(oacc[f][0] * invA);
        vA.y = wmma::__float_to_tf32(oacc[f][1] * invA);
        vB.x = wmma::__float_to_tf32(oacc[f][2] * invB);
        vB.y = wmma::__float_to_tf32(oacc[f][3] * invB);
        *(float2*)(aoA + f * 8) = vA;
        *(float2*)(aoB + f * 8) = vB;
    }
}

// ---------------- launch ----------------
extern "C" void kernel_launch(void* const* d_in, const int* in_sizes, int n_in,
                              void* d_out, int out_size)
{
    const float* x    = (const float*)d_in[0];
    const float* Wqkv = (const float*)d_in[1];
    const float* bqkv = (const float*)d_in[2];
    const float* Wout = (const float*)d_in[3];
    const float* bout = (const float*)d_in[4];
    float* out = (float*)d_out;

    cudaFuncSetAttribute(gemm_tf32,
                         cudaFuncAttributeMaxDynamicSharedMemorySize, GEMM_SMEM_BYTES);
    cudaFuncSetAttribute(attn_kernel,
                         cudaFuncAttributeMaxDynamicSharedMemorySize, ATT_SMEM_BYTES);

    // prep: round all operands to tf32 in one launch
    round_all<<<(PREP_F4 + 255) / 256, 256>>>(
        (const float4*)x, (const float4*)Wqkv, (const float4*)Wout);

    // 1) QKV projection
    dim3 g1(3 * C_SZ / BN, M_SZ / BM);   // (24, 64)
    gemm_tf32<<<g1, 128, GEMM_SMEM_BYTES>>>(bqkv, nullptr, M_SZ, 3 * C_SZ, C_SZ, 0);

    // 2) causal flash attention
    dim3 g2(T_SZ / AQ, B_SZ * H_SZ);     // (16, 64)
    attn_kernel<<<g2, 256, ATT_SMEM_BYTES>>>();

    // 3) output projection
    dim3 g3(C_SZ / BN, M_SZ / BM);       // (8, 64)
    gemm_tf32<<<g3, 128, GEMM_SMEM_BYTES>>>(bout, out, M_SZ, C_SZ, C_SZ, 1);
}

// round 14
// speedup vs baseline: 1.0390x; 1.0390x over previous
#include <cuda_runtime.h>
#include <mma.h>
#include <math.h>
#include <stdint.h>

using namespace nvcuda;

#define B_SZ 4
#define T_SZ 2048
#define C_SZ 1024
#define H_SZ 16
#define D_SZ 64
#define M_SZ (B_SZ * T_SZ)   // 8192

// ---------------- scratch (static device globals; no allocation) ----------------
__device__ float g_q[(size_t)B_SZ * H_SZ * T_SZ * D_SZ];   // [B,H,T,D] tf32-rounded
__device__ float g_k[(size_t)B_SZ * H_SZ * T_SZ * D_SZ];
__device__ float g_v[(size_t)B_SZ * H_SZ * T_SZ * D_SZ];
__device__ float g_ao[(size_t)B_SZ * T_SZ * C_SZ];         // attention out, tf32-rounded
__device__ float g_xr[(size_t)M_SZ * C_SZ];                // x, tf32-rounded
__device__ float g_wqkv[(size_t)C_SZ * 3 * C_SZ];          // W_qkv, tf32-rounded
__device__ float g_wout[(size_t)C_SZ * C_SZ];              // W_out, tf32-rounded

// ---------------- cp.async helpers ----------------
__device__ __forceinline__ void cp_async16(void* smem, const void* gmem) {
    uint32_t s = (uint32_t)__cvta_generic_to_shared(smem);
    asm volatile("cp.async.cg.shared.global [%0], [%1], 16;\n" :: "r"(s), "l"(gmem));
}
__device__ __forceinline__ void cp_commit() {
    asm volatile("cp.async.commit_group;\n");
}
template<int N>
__device__ __forceinline__ void cp_wait() {
    asm volatile("cp.async.wait_group %0;\n" :: "n"(N));
}

// ---------------- raw tf32 mma (PTX-defined fragment layout) ----------------
__device__ __forceinline__ void mma_tf32(float* c, const uint32_t* a, const uint32_t* b) {
    asm volatile(
        "mma.sync.aligned.m16n8k8.row.col.f32.tf32.tf32.f32 "
        "{%0,%1,%2,%3}, {%4,%5,%6,%7}, {%8,%9}, {%0,%1,%2,%3};\n"
        : "+f"(c[0]), "+f"(c[1]), "+f"(c[2]), "+f"(c[3])
        : "r"(a[0]), "r"(a[1]), "r"(a[2]), "r"(a[3]), "r"(b[0]), "r"(b[1]));
}

// ---------------- prep: round all three operand arrays to tf32 (one launch) -----
#define XR_F4   (M_SZ * C_SZ / 4)            // 2,097,152
#define WQKV_F4 (3 * C_SZ * C_SZ / 4)        //   786,432
#define WOUT_F4 (C_SZ * C_SZ / 4)            //   262,144
#define PREP_F4 (XR_F4 + WQKV_F4 + WOUT_F4)  // 3,145,728

__global__ void round_all(const float4* __restrict__ x,
                          const float4* __restrict__ wqkv,
                          const float4* __restrict__ wout)
{
    int i = blockIdx.x * blockDim.x + threadIdx.x;
    if (i >= PREP_F4) return;
    const float4* src;
    float4* dst;
    if (i < XR_F4) {
        src = x + i;                     dst = (float4*)g_xr + i;
    } else if (i < XR_F4 + WQKV_F4) {
        int j = i - XR_F4;
        src = wqkv + j;                  dst = (float4*)g_wqkv + j;
    } else {
        int j = i - XR_F4 - WQKV_F4;
        src = wout + j;                  dst = (float4*)g_wout + j;
    }
    float4 v = *src;
    v.x = wmma::__float_to_tf32(v.x);
    v.y = wmma::__float_to_tf32(v.y);
    v.z = wmma::__float_to_tf32(v.z);
    v.w = wmma::__float_to_tf32(v.w);
    *dst = v;
}

// ---------------- GEMM v3b: raw m16n8k8 mma, 128x128 CTA, GS=2, 3 CTAs/SM -------
// (unchanged from R12)
#define BM 128
#define BN 128
#define BK 32
#define GS 2
#define LDA (BK + 4)    // 36
#define LDB (BN + 4)    // 132
#define A_STG (BM * LDA)          // 4608 floats
#define B_STG (BK * LDB)          // 4224 floats
#define GEMM_SMEM_BYTES (GS * (A_STG + B_STG) * 4)   // 70656 B -> 3 CTAs/SM

__global__ void __launch_bounds__(128, 3) gemm_tf32(
    const float* __restrict__ bias, float* __restrict__ Cout,
    int M, int N, int K, int mode)
{
    extern __shared__ float gsm[];
    float* Ash = gsm;
    float* Bsh = gsm + GS * A_STG;

    const float* Aptr = (mode == 1) ? g_ao : g_xr;
    const float* Bm   = (mode == 1) ? g_wout : g_wqkv;

    int tid  = threadIdx.x;
    int warp = tid >> 5;
    int lane = tid & 31;
    int wm = warp >> 1;
    int wn = warp & 1;
    int g  = lane >> 2;
    int t  = lane & 3;
    int m0 = blockIdx.y * BM;
    int n0 = blockIdx.x * BN;

    float acc[4][8][4];
    #pragma unroll
    for (int i = 0; i < 4; i++)
        #pragma unroll
        for (int f = 0; f < 8; f++)
            #pragma unroll
            for (int e = 0; e < 4; e++) acc[i][f][e] = 0.f;

    int ar = tid >> 3,  ac = (tid & 7)  * 4;
    int br = tid >> 5,  bc = (tid & 31) * 4;

    auto load_tile = [&](int stage, int k0) {
        float* As = Ash + stage * A_STG;
        float* Bs = Bsh + stage * B_STG;
        #pragma unroll
        for (int i = 0; i < 8; i++) {
            int r = ar + i * 16;
            cp_async16(As + r * LDA + ac, Aptr + (size_t)(m0 + r) * K + k0 + ac);
        }
        #pragma unroll
        for (int i = 0; i < 8; i++) {
            int r = br + i * 4;
            cp_async16(Bs + r * LDB + bc, Bm + (size_t)(k0 + r) * N + n0 + bc);
        }
        cp_commit();
    };

    int KT = K / BK;
    load_tile(0, 0);

    for (int kt = 0; kt < KT; ++kt) {
        __syncthreads();
        if (kt + 1 < KT) {
            load_tile((kt + 1) & 1, (kt + 1) * BK);
            cp_wait<1>();
        } else {
            cp_wait<0>();
        }
        __syncthreads();

        float* As = Ash + (kt & 1) * A_STG;
        float* Bs = Bsh + (kt & 1) * B_STG;

        #pragma unroll
        for (int kk = 0; kk < BK; kk += 8) {
            uint32_t a[4][4];
            #pragma unroll
            for (int i = 0; i < 4; i++) {
                int rA = wm * 64 + i * 16 + g;
                a[i][0] = __float_as_uint(As[(rA    ) * LDA + kk + t]);
                a[i][1] = __float_as_uint(As[(rA + 8) * LDA + kk + t]);
                a[i][2] = __float_as_uint(As[(rA    ) * LDA + kk + t + 4]);
                a[i][3] = __float_as_uint(As[(rA + 8) * LDA + kk + t + 4]);
            }
            #pragma unroll
            for (int f = 0; f < 8; f++) {
                uint32_t bb[2];
                int nB = wn * 64 + f * 8 + g;
                bb[0] = __float_as_uint(Bs[(kk + t)     * LDB + nB]);
                bb[1] = __float_as_uint(Bs[(kk + t + 4) * LDB + nB]);
                #pragma unroll
                for (int i = 0; i < 4; i++)
                    mma_tf32(acc[i][f], a[i], bb);
            }
        }
    }
    __syncthreads();

    float* stg = Ash + warp * 1152;
    #pragma unroll
    for (int i = 0; i < 4; i++) {
        #pragma unroll
        for (int f = 0; f < 8; f++) {
            *(float2*)(stg + (g    ) * 68 + f * 8 + 2 * t) = make_float2(acc[i][f][0], acc[i][f][1]);
            *(float2*)(stg + (g + 8) * 68 + f * 8 + 2 * t) = make_float2(acc[i][f][2], acc[i][f][3]);
        }
        __syncwarp();
        #pragma unroll
        for (int e = 0; e < 8; e++) {
            int idx = lane + e * 32;
            int rr = idx >> 4, cc = (idx & 15) * 4;
            int m = m0 + wm * 64 + i * 16 + rr;
            int n = n0 + wn * 64 + cc;
            float4 v  = *(float4*)(stg + rr * 68 + cc);
            float4 bv = *(const float4*)(bias + n);
            v.x += bv.x; v.y += bv.y; v.z += bv.z; v.w += bv.w;
            if (mode == 0) {
                int third = n >> 10, c = n & 1023;
                int h = c >> 6, d = c & 63;
                int b = m >> 11, tt = m & 2047;
                float* dst = (third == 0) ? g_q : (third == 1) ? g_k : g_v;
                v.x = wmma::__float_to_tf32(v.x);
                v.y = wmma::__float_to_tf32(v.y);
                v.z = wmma::__float_to_tf32(v.z);
                v.w = wmma::__float_to_tf32(v.w);
                *(float4*)(dst + (((size_t)(b * H_SZ + h)) * T_SZ + tt) * D_SZ + d) = v;
            } else {
                *(float4*)(Cout + (size_t)m * N + n) = v;
            }
        }
        __syncwarp();
    }
}

// ---------------- Flash attention v3: shfl P-transpose + 2-stage K/V ring --------
// One CTA per (b,h,128-row Q tile). 8 warps x 16 rows. 2 CTAs/SM (no spills).
// K/V double-buffered: stage kt+1 flies while kt computes (GEMM-proven ordering).
#define AQ 128
#define AK 64
#define ALD 68
#define KV_STG (AK * ALD)                 // 4352 floats
#define ATT_SMEM_FLOATS (AQ * ALD + 2 * KV_STG + 2 * KV_STG)
#define ATT_SMEM_BYTES  (ATT_SMEM_FLOATS * 4)   // 104448 B -> 2 CTAs/SM

__global__ void __launch_bounds__(256, 2) attn_kernel()
{
    extern __shared__ float smbuf[];
    float* Qsh = smbuf;
    float* Ksh = Qsh + AQ * ALD;          // 2 stages
    float* Vsh = Ksh + 2 * KV_STG;        // 2 stages

    int qt = gridDim.x - 1 - blockIdx.x;   // longest tiles first
    int q0 = qt * AQ;
    int bh = blockIdx.y;
    int b = bh >> 4, h = bh & 15;

    const float* Qb = g_q + (size_t)bh * T_SZ * D_SZ;
    const float* Kb = g_k + (size_t)bh * T_SZ * D_SZ;
    const float* Vb = g_v + (size_t)bh * T_SZ * D_SZ;

    int tid  = threadIdx.x;
    int warp = tid >> 5;
    int lane = tid & 31;
    int r0 = warp * 16;
    int g = lane >> 2;
    int t = lane & 3;
    int rowA = r0 + g, rowB = rowA + 8;
    int qiA = q0 + rowA, qiB = q0 + rowB;

    // load Q tile with 0.125 scale folded in
    #pragma unroll
    for (int i = 0; i < 8; i++) {
        int idx = tid + i * 256;
        int r = idx >> 4, c = (idx & 15) * 4;
        float4 v = *(const float4*)(Qb + (size_t)(q0 + r) * D_SZ + c);
        v.x *= 0.125f; v.y *= 0.125f; v.z *= 0.125f; v.w *= 0.125f;
        *(float4*)(Qsh + r * ALD + c) = v;
    }

    float oacc[8][4];
    #pragma unroll
    for (int f = 0; f < 8; f++)
        #pragma unroll
        for (int e = 0; e < 4; e++) oacc[f][e] = 0.f;

    float laccA = 0.f, laccB = 0.f;

    int kr = tid >> 4, kc = (tid & 15) * 4;
    auto fill_kv = [&](int stage, int k0) {
        float* Ks = Ksh + stage * KV_STG;
        float* Vs = Vsh + stage * KV_STG;
        #pragma unroll
        for (int i = 0; i < 4; i++) {
            int r = kr + i * 16;
            cp_async16(Ks + r * ALD + kc, Kb + (size_t)(k0 + r) * D_SZ + kc);
            cp_async16(Vs + r * ALD + kc, Vb + (size_t)(k0 + r) * D_SZ + kc);
        }
        cp_commit();
    };

    int nkt = 2 * qt + 2;
    int srcA = (lane & 0x1C) | (t >> 1);   // 4g + t/2
    int srcB = srcA + 2;
    bool odd = (t & 1);

    fill_kv(0, 0);

    for (int kt = 0; kt < nkt; ++kt) {
        int k0 = kt * AK;
        __syncthreads();                      // all warps done reading stage (kt+1)&1
        if (kt + 1 < nkt) {
            fill_kv((kt + 1) & 1, k0 + AK);   // next tile flies during compute
            cp_wait<1>();                     // stage kt landed
        } else {
            cp_wait<0>();
        }
        __syncthreads();                      // stage kt visible

        float* Ks = Ksh + (kt & 1) * KV_STG;
        float* Vs = Vsh + (kt & 1) * KV_STG;

        // ---- S = (Q*0.125) @ K^T, in registers ----
        float sacc[8][4];
        #pragma unroll
        for (int f = 0; f < 8; f++)
            #pragma unroll
            for (int e = 0; e < 4; e++) sacc[f][e] = 0.f;

        #pragma unroll
        for (int kk = 0; kk < 64; kk += 8) {
            uint32_t a[4];
            a[0] = __float_as_uint(Qsh[rowA * ALD + kk + t]);
            a[1] = __float_as_uint(Qsh[rowB * ALD + kk + t]);
            a[2] = __float_as_uint(Qsh[rowA * ALD + kk + t + 4]);
            a[3] = __float_as_uint(Qsh[rowB * ALD + kk + t + 4]);
            #pragma unroll
            for (int f = 0; f < 8; f++) {
                uint32_t bb[2];
                bb[0] = __float_as_uint(Ks[(f * 8 + g) * ALD + kk + t]);
                bb[1] = __float_as_uint(Ks[(f * 8 + g) * ALD + kk + t + 4]);
                mma_tf32(sacc[f], a, bb);
            }
        }

        // ---- softmax numerator in registers ----
        #pragma unroll
        for (int f = 0; f < 8; f++) {
            int c0 = k0 + f * 8 + 2 * t;
            float p0 = (c0     <= qiA) ? __expf(fminf(sacc[f][0], 60.f)) : 0.f;
            float p1 = (c0 + 1 <= qiA) ? __expf(fminf(sacc[f][1], 60.f)) : 0.f;
            float p2 = (c0     <= qiB) ? __expf(fminf(sacc[f][2], 60.f)) : 0.f;
            float p3 = (c0 + 1 <= qiB) ? __expf(fminf(sacc[f][3], 60.f)) : 0.f;
            p0 = wmma::__float_to_tf32(p0);
            p1 = wmma::__float_to_tf32(p1);
            p2 = wmma::__float_to_tf32(p2);
            p3 = wmma::__float_to_tf32(p3);
            laccA += p0 + p1;
            laccB += p2 + p3;
            sacc[f][0] = p0; sacc[f][1] = p1; sacc[f][2] = p2; sacc[f][3] = p3;
        }

        // ---- O += P @ V; P relayout C-frag -> A-frag via quad shuffles ----
        #pragma unroll
        for (int fk = 0; fk < 8; fk++) {
            float x0 = __shfl_sync(0xffffffffu, sacc[fk][0], srcA);
            float x1 = __shfl_sync(0xffffffffu, sacc[fk][1], srcA);
            float y0 = __shfl_sync(0xffffffffu, sacc[fk][2], srcA);
            float y1 = __shfl_sync(0xffffffffu, sacc[fk][3], srcA);
            float z0 = __shfl_sync(0xffffffffu, sacc[fk][0], srcB);
            float z1 = __shfl_sync(0xffffffffu, sacc[fk][1], srcB);
            float w0 = __shfl_sync(0xffffffffu, sacc[fk][2], srcB);
            float w1 = __shfl_sync(0xffffffffu, sacc[fk][3], srcB);
            uint32_t a[4];
            a[0] = __float_as_uint(odd ? x1 : x0);   // P[rowA][8fk + t]
            a[1] = __float_as_uint(odd ? y1 : y0);   // P[rowB][8fk + t]
            a[2] = __float_as_uint(odd ? z1 : z0);   // P[rowA][8fk + t+4]
            a[3] = __float_as_uint(odd ? w1 : w0);   // P[rowB][8fk + t+4]
            int kk = fk * 8;
            #pragma unroll
            for (int f = 0; f < 8; f++) {
                uint32_t bb[2];
                bb[0] = __float_as_uint(Vs[(kk + t)     * ALD + f * 8 + g]);
                bb[1] = __float_as_uint(Vs[(kk + t + 4) * ALD + f * 8 + g]);
                mma_tf32(oacc[f], a, bb);
            }
        }
    }

    // ---- row-sum reduction across the quad, normalize O, write directly ----
    laccA += __shfl_xor_sync(0xffffffffu, laccA, 1);
    laccA += __shfl_xor_sync(0xffffffffu, laccA, 2);
    laccB += __shfl_xor_sync(0xffffffffu, laccB, 1);
    laccB += __shfl_xor_sync(0xffffffffu, laccB, 2);
    float invA = 1.0f / laccA;
    float invB = 1.0f / laccB;

    float* aoA = g_ao + (size_t)(b * T_SZ + q0 + rowA) * C_SZ + h * D_SZ + 2 * t;
    float* aoB = g_ao + (size_t)(b * T_SZ + q0 + rowB) * C_SZ + h * D_SZ + 2 * t;
    #pragma unroll
    for (int f = 0; f < 8; f++) {
        float2 vA, vB;
        vA.x = wmma::__float_to_tf32(oacc[f][0] * invA);
        vA.y = wmma::__float_to_tf32(oacc[f][1] * invA);
        vB.x = wmma::__float_to_tf32(oacc[f][2] * invB);
        vB.y = wmma::__float_to_tf32(oacc[f][3] * invB);
        *(float2*)(aoA + f * 8) = vA;
        *(float2*)(aoB + f * 8) = vB;
    }
}

// ---------------- launch ----------------
extern "C" void kernel_launch(void* const* d_in, const int* in_sizes, int n_in,
                              void* d_out, int out_size)
{
    const float* x    = (const float*)d_in[0];
    const float* Wqkv = (const float*)d_in[1];
    const float* bqkv = (const float*)d_in[2];
    const float* Wout = (const float*)d_in[3];
    const float* bout = (const float*)d_in[4];
    float* out = (float*)d_out;

    cudaFuncSetAttribute(gemm_tf32,
                         cudaFuncAttributeMaxDynamicSharedMemorySize, GEMM_SMEM_BYTES);
    cudaFuncSetAttribute(attn_kernel,
                         cudaFuncAttributeMaxDynamicSharedMemorySize, ATT_SMEM_BYTES);

    // prep: round all operands to tf32 in one launch
    round_all<<<(PREP_F4 + 255) / 256, 256>>>(
        (const float4*)x, (const float4*)Wqkv, (const float4*)Wout);

    // 1) QKV projection
    dim3 g1(3 * C_SZ / BN, M_SZ / BM);   // (24, 64)
    gemm_tf32<<<g1, 128, GEMM_SMEM_BYTES>>>(bqkv, nullptr, M_SZ, 3 * C_SZ, C_SZ, 0);

    // 2) causal flash attention
    dim3 g2(T_SZ / AQ, B_SZ * H_SZ);     // (16, 64)
    attn_kernel<<<g2, 256, ATT_SMEM_BYTES>>>();

    // 3) output projection
    dim3 g3(C_SZ / BN, M_SZ / BM);       // (8, 64)
    gemm_tf32<<<g3, 128, GEMM_SMEM_BYTES>>>(bout, out, M_SZ, C_SZ, C_SZ, 1);
}

// round 15
// speedup vs baseline: 1.1464x; 1.1033x over previous
#include <cuda_runtime.h>
#include <mma.h>
#include <math.h>
#include <stdint.h>

using namespace nvcuda;

#define B_SZ 4
#define T_SZ 2048
#define C_SZ 1024
#define H_SZ 16
#define D_SZ 64
#define M_SZ (B_SZ * T_SZ)   // 8192

// ---------------- scratch (static device globals; no allocation) ----------------
__device__ float g_q[(size_t)B_SZ * H_SZ * T_SZ * D_SZ];   // [B,H,T,D] tf32-rounded
__device__ float g_k[(size_t)B_SZ * H_SZ * T_SZ * D_SZ];
__device__ float g_v[(size_t)B_SZ * H_SZ * T_SZ * D_SZ];
__device__ float g_ao[(size_t)B_SZ * T_SZ * C_SZ];         // attention out, tf32-rounded
__device__ float g_xr[(size_t)M_SZ * C_SZ];                // x, tf32-rounded
__device__ float g_wqkv[(size_t)C_SZ * 3 * C_SZ];          // W_qkv, tf32-rounded
__device__ float g_wout[(size_t)C_SZ * C_SZ];              // W_out, tf32-rounded

// ---------------- cp.async helpers ----------------
__device__ __forceinline__ void cp_async16(void* smem, const void* gmem) {
    uint32_t s = (uint32_t)__cvta_generic_to_shared(smem);
    asm volatile("cp.async.cg.shared.global [%0], [%1], 16;\n" :: "r"(s), "l"(gmem));
}
__device__ __forceinline__ void cp_commit() {
    asm volatile("cp.async.commit_group;\n");
}
template<int N>
__device__ __forceinline__ void cp_wait() {
    asm volatile("cp.async.wait_group %0;\n" :: "n"(N));
}

// ---------------- raw tf32 mma (PTX-defined fragment layout) ----------------
__device__ __forceinline__ void mma_tf32(float* c, const uint32_t* a, const uint32_t* b) {
    asm volatile(
        "mma.sync.aligned.m16n8k8.row.col.f32.tf32.tf32.f32 "
        "{%0,%1,%2,%3}, {%4,%5,%6,%7}, {%8,%9}, {%0,%1,%2,%3};\n"
        : "+f"(c[0]), "+f"(c[1]), "+f"(c[2]), "+f"(c[3])
        : "r"(a[0]), "r"(a[1]), "r"(a[2]), "r"(a[3]), "r"(b[0]), "r"(b[1]));
}

// ---------------- prep: round all three operand arrays to tf32 (one launch) -----
#define XR_F4   (M_SZ * C_SZ / 4)            // 2,097,152
#define WQKV_F4 (3 * C_SZ * C_SZ / 4)        //   786,432
#define WOUT_F4 (C_SZ * C_SZ / 4)            //   262,144
#define PREP_F4 (XR_F4 + WQKV_F4 + WOUT_F4)  // 3,145,728

__global__ void round_all(const float4* __restrict__ x,
                          const float4* __restrict__ wqkv,
                          const float4* __restrict__ wout)
{
    int i = blockIdx.x * blockDim.x + threadIdx.x;
    if (i >= PREP_F4) return;
    const float4* src;
    float4* dst;
    if (i < XR_F4) {
        src = x + i;                     dst = (float4*)g_xr + i;
    } else if (i < XR_F4 + WQKV_F4) {
        int j = i - XR_F4;
        src = wqkv + j;                  dst = (float4*)g_wqkv + j;
    } else {
        int j = i - XR_F4 - WQKV_F4;
        src = wout + j;                  dst = (float4*)g_wout + j;
    }
    float4 v = *src;
    v.x = wmma::__float_to_tf32(v.x);
    v.y = wmma::__float_to_tf32(v.y);
    v.z = wmma::__float_to_tf32(v.z);
    v.w = wmma::__float_to_tf32(v.w);
    *dst = v;
}

// ---------------- GEMM v3c: raw m16n8k8, 128x128 CTA, GS=2, conflict-free B -----
// LDB = 136 (== 8 mod 32): B-frag loads hit bank (8t+g) -> bijective, 0 conflicts.
#define BM 128
#define BN 128
#define BK 32
#define GS 2
#define LDA (BK + 4)     // 36  (A loads already conflict-free: bank 4g+t)
#define LDB (BN + 8)     // 136 (was 132 -> 2-way conflicts)
#define A_STG (BM * LDA)          // 4608 floats
#define B_STG (BK * LDB)          // 4352 floats
#define GEMM_SMEM_BYTES (GS * (A_STG + B_STG) * 4)   // 71680 B -> 3 CTAs/SM

__global__ void __launch_bounds__(128, 3) gemm_tf32(
    const float* __restrict__ bias, float* __restrict__ Cout,
    int M, int N, int K, int mode)
{
    extern __shared__ float gsm[];
    float* Ash = gsm;
    float* Bsh = gsm + GS * A_STG;

    const float* Aptr = (mode == 1) ? g_ao : g_xr;
    const float* Bm   = (mode == 1) ? g_wout : g_wqkv;

    int tid  = threadIdx.x;
    int warp = tid >> 5;
    int lane = tid & 31;
    int wm = warp >> 1;
    int wn = warp & 1;
    int g  = lane >> 2;
    int t  = lane & 3;
    int m0 = blockIdx.y * BM;
    int n0 = blockIdx.x * BN;

    float acc[4][8][4];
    #pragma unroll
    for (int i = 0; i < 4; i++)
        #pragma unroll
        for (int f = 0; f < 8; f++)
            #pragma unroll
            for (int e = 0; e < 4; e++) acc[i][f][e] = 0.f;

    int ar = tid >> 3,  ac = (tid & 7)  * 4;
    int br = tid >> 5,  bc = (tid & 31) * 4;

    auto load_tile = [&](int stage, int k0) {
        float* As = Ash + stage * A_STG;
        float* Bs = Bsh + stage * B_STG;
        #pragma unroll
        for (int i = 0; i < 8; i++) {
            int r = ar + i * 16;
            cp_async16(As + r * LDA + ac, Aptr + (size_t)(m0 + r) * K + k0 + ac);
        }
        #pragma unroll
        for (int i = 0; i < 8; i++) {
            int r = br + i * 4;
            cp_async16(Bs + r * LDB + bc, Bm + (size_t)(k0 + r) * N + n0 + bc);
        }
        cp_commit();
    };

    int KT = K / BK;
    load_tile(0, 0);

    for (int kt = 0; kt < KT; ++kt) {
        __syncthreads();
        if (kt + 1 < KT) {
            load_tile((kt + 1) & 1, (kt + 1) * BK);
            cp_wait<1>();
        } else {
            cp_wait<0>();
        }
        __syncthreads();

        float* As = Ash + (kt & 1) * A_STG;
        float* Bs = Bsh + (kt & 1) * B_STG;

        #pragma unroll
        for (int kk = 0; kk < BK; kk += 8) {
            uint32_t a[4][4];
            #pragma unroll
            for (int i = 0; i < 4; i++) {
                int rA = wm * 64 + i * 16 + g;
                a[i][0] = __float_as_uint(As[(rA    ) * LDA + kk + t]);
                a[i][1] = __float_as_uint(As[(rA + 8) * LDA + kk + t]);
                a[i][2] = __float_as_uint(As[(rA    ) * LDA + kk + t + 4]);
                a[i][3] = __float_as_uint(As[(rA + 8) * LDA + kk + t + 4]);
            }
            #pragma unroll
            for (int f = 0; f < 8; f++) {
                uint32_t bb[2];
                int nB = wn * 64 + f * 8 + g;
                bb[0] = __float_as_uint(Bs[(kk + t)     * LDB + nB]);
                bb[1] = __float_as_uint(Bs[(kk + t + 4) * LDB + nB]);
                #pragma unroll
                for (int i = 0; i < 4; i++)
                    mma_tf32(acc[i][f], a[i], bb);
            }
        }
    }
    __syncthreads();

    float* stg = Ash + warp * 1152;
    #pragma unroll
    for (int i = 0; i < 4; i++) {
        #pragma unroll
        for (int f = 0; f < 8; f++) {
            *(float2*)(stg + (g    ) * 68 + f * 8 + 2 * t) = make_float2(acc[i][f][0], acc[i][f][1]);
            *(float2*)(stg + (g + 8) * 68 + f * 8 + 2 * t) = make_float2(acc[i][f][2], acc[i][f][3]);
        }
        __syncwarp();
        #pragma unroll
        for (int e = 0; e < 8; e++) {
            int idx = lane + e * 32;
            int rr = idx >> 4, cc = (idx & 15) * 4;
            int m = m0 + wm * 64 + i * 16 + rr;
            int n = n0 + wn * 64 + cc;
            float4 v  = *(float4*)(stg + rr * 68 + cc);
            float4 bv = *(const float4*)(bias + n);
            v.x += bv.x; v.y += bv.y; v.z += bv.z; v.w += bv.w;
            if (mode == 0) {
                int third = n >> 10, c = n & 1023;
                int h = c >> 6, d = c & 63;
                int b = m >> 11, tt = m & 2047;
                float* dst = (third == 0) ? g_q : (third == 1) ? g_k : g_v;
                v.x = wmma::__float_to_tf32(v.x);
                v.y = wmma::__float_to_tf32(v.y);
                v.z = wmma::__float_to_tf32(v.z);
                v.w = wmma::__float_to_tf32(v.w);
                *(float4*)(dst + (((size_t)(b * H_SZ + h)) * T_SZ + tt) * D_SZ + d) = v;
            } else {
                *(float4*)(Cout + (size_t)m * N + n) = v;
            }
        }
        __syncwarp();
    }
}

// ---------------- Flash attention v4: shfl P-transpose + K/V ring, V pitch 72 ----
// V gets its own pitch (72 == 8 mod 32): PV B-frag loads bank (8t+g) -> 0 conflicts.
#define AQ 128
#define AK 64
#define ALD 68            // Q/K pitch (loads hit bank 4g+t: conflict-free)
#define VLD 72            // V pitch (was 68 -> 2-way conflicts)
#define K_STG (AK * ALD)                  // 4352 floats
#define V_STG (AK * VLD)                  // 4608 floats
#define ATT_SMEM_FLOATS (AQ * ALD + 2 * K_STG + 2 * V_STG)
#define ATT_SMEM_BYTES  (ATT_SMEM_FLOATS * 4)   // 106496 B -> 2 CTAs/SM

__global__ void __launch_bounds__(256, 2) attn_kernel()
{
    extern __shared__ float smbuf[];
    float* Qsh = smbuf;
    float* Ksh = Qsh + AQ * ALD;          // 2 stages
    float* Vsh = Ksh + 2 * K_STG;         // 2 stages

    int qt = gridDim.x - 1 - blockIdx.x;   // longest tiles first
    int q0 = qt * AQ;
    int bh = blockIdx.y;
    int b = bh >> 4, h = bh & 15;

    const float* Qb = g_q + (size_t)bh * T_SZ * D_SZ;
    const float* Kb = g_k + (size_t)bh * T_SZ * D_SZ;
    const float* Vb = g_v + (size_t)bh * T_SZ * D_SZ;

    int tid  = threadIdx.x;
    int warp = tid >> 5;
    int lane = tid & 31;
    int r0 = warp * 16;
    int g = lane >> 2;
    int t = lane & 3;
    int rowA = r0 + g, rowB = rowA + 8;
    int qiA = q0 + rowA, qiB = q0 + rowB;

    // load Q tile with 0.125 scale folded in
    #pragma unroll
    for (int i = 0; i < 8; i++) {
        int idx = tid + i * 256;
        int r = idx >> 4, c = (idx & 15) * 4;
        float4 v = *(const float4*)(Qb + (size_t)(q0 + r) * D_SZ + c);
        v.x *= 0.125f; v.y *= 0.125f; v.z *= 0.125f; v.w *= 0.125f;
        *(float4*)(Qsh + r * ALD + c) = v;
    }

    float oacc[8][4];
    #pragma unroll
    for (int f = 0; f < 8; f++)
        #pragma unroll
        for (int e = 0; e < 4; e++) oacc[f][e] = 0.f;

    float laccA = 0.f, laccB = 0.f;

    int kr = tid >> 4, kc = (tid & 15) * 4;
    auto fill_kv = [&](int stage, int k0) {
        float* Ks = Ksh + stage * K_STG;
        float* Vs = Vsh + stage * V_STG;
        #pragma unroll
        for (int i = 0; i < 4; i++) {
            int r = kr + i * 16;
            cp_async16(Ks + r * ALD + kc, Kb + (size_t)(k0 + r) * D_SZ + kc);
            cp_async16(Vs + r * VLD + kc, Vb + (size_t)(k0 + r) * D_SZ + kc);
        }
        cp_commit();
    };

    int nkt = 2 * qt + 2;
    int srcA = (lane & 0x1C) | (t >> 1);   // 4g + t/2
    int srcB = srcA + 2;
    bool odd = (t & 1);

    fill_kv(0, 0);

    for (int kt = 0; kt < nkt; ++kt) {
        int k0 = kt * AK;
        __syncthreads();                      // all warps done reading stage (kt+1)&1
        if (kt + 1 < nkt) {
            fill_kv((kt + 1) & 1, k0 + AK);   // next tile flies during compute
            cp_wait<1>();                     // stage kt landed
        } else {
            cp_wait<0>();
        }
        __syncthreads();                      // stage kt visible

        float* Ks = Ksh + (kt & 1) * K_STG;
        float* Vs = Vsh + (kt & 1) * V_STG;

        // ---- S = (Q*0.125) @ K^T, in registers ----
        float sacc[8][4];
        #pragma unroll
        for (int f = 0; f < 8; f++)
            #pragma unroll
            for (int e = 0; e < 4; e++) sacc[f][e] = 0.f;

        #pragma unroll
        for (int kk = 0; kk < 64; kk += 8) {
            uint32_t a[4];
            a[0] = __float_as_uint(Qsh[rowA * ALD + kk + t]);
            a[1] = __float_as_uint(Qsh[rowB * ALD + kk + t]);
            a[2] = __float_as_uint(Qsh[rowA * ALD + kk + t + 4]);
            a[3] = __float_as_uint(Qsh[rowB * ALD + kk + t + 4]);
            #pragma unroll
            for (int f = 0; f < 8; f++) {
                uint32_t bb[2];
                bb[0] = __float_as_uint(Ks[(f * 8 + g) * ALD + kk + t]);
                bb[1] = __float_as_uint(Ks[(f * 8 + g) * ALD + kk + t + 4]);
                mma_tf32(sacc[f], a, bb);
            }
        }

        // ---- softmax numerator in registers ----
        #pragma unroll
        for (int f = 0; f < 8; f++) {
            int c0 = k0 + f * 8 + 2 * t;
            float p0 = (c0     <= qiA) ? __expf(fminf(sacc[f][0], 60.f)) : 0.f;
            float p1 = (c0 + 1 <= qiA) ? __expf(fminf(sacc[f][1], 60.f)) : 0.f;
            float p2 = (c0     <= qiB) ? __expf(fminf(sacc[f][2], 60.f)) : 0.f;
            float p3 = (c0 + 1 <= qiB) ? __expf(fminf(sacc[f][3], 60.f)) : 0.f;
            p0 = wmma::__float_to_tf32(p0);
            p1 = wmma::__float_to_tf32(p1);
            p2 = wmma::__float_to_tf32(p2);
            p3 = wmma::__float_to_tf32(p3);
            laccA += p0 + p1;
            laccB += p2 + p3;
            sacc[f][0] = p0; sacc[f][1] = p1; sacc[f][2] = p2; sacc[f][3] = p3;
        }

        // ---- O += P @ V; P relayout C-frag -> A-frag via quad shuffles ----
        #pragma unroll
        for (int fk = 0; fk < 8; fk++) {
            float x0 = __shfl_sync(0xffffffffu, sacc[fk][0], srcA);
            float x1 = __shfl_sync(0xffffffffu, sacc[fk][1], srcA);
            float y0 = __shfl_sync(0xffffffffu, sacc[fk][2], srcA);
            float y1 = __shfl_sync(0xffffffffu, sacc[fk][3], srcA);
            float z0 = __shfl_sync(0xffffffffu, sacc[fk][0], srcB);
            float z1 = __shfl_sync(0xffffffffu, sacc[fk][1], srcB);
            float w0 = __shfl_sync(0xffffffffu, sacc[fk][2], srcB);
            float w1 = __shfl_sync(0xffffffffu, sacc[fk][3], srcB);
            uint32_t a[4];
            a[0] = __float_as_uint(odd ? x1 : x0);   // P[rowA][8fk + t]
            a[1] = __float_as_uint(odd ? y1 : y0);   // P[rowB][8fk + t]
            a[2] = __float_as_uint(odd ? z1 : z0);   // P[rowA][8fk + t+4]
            a[3] = __float_as_uint(odd ? w1 : w0);   // P[rowB][8fk + t+4]
            int kk = fk * 8;
            #pragma unroll
            for (int f = 0; f < 8; f++) {
                uint32_t bb[2];
                bb[0] = __float_as_uint(Vs[(kk + t)     * VLD + f * 8 + g]);
                bb[1] = __float_as_uint(Vs[(kk + t + 4) * VLD + f * 8 + g]);
                mma_tf32(oacc[f], a, bb);
            }
        }
    }

    // ---- row-sum reduction across the quad, normalize O, write directly ----
    laccA += __shfl_xor_sync(0xffffffffu, laccA, 1);
    laccA += __shfl_xor_sync(0xffffffffu, laccA, 2);
    laccB += __shfl_xor_sync(0xffffffffu, laccB, 1);
    laccB += __shfl_xor_sync(0xffffffffu, laccB, 2);
    float invA = 1.0f / laccA;
    float invB = 1.0f / laccB;

    float* aoA = g_ao + (size_t)(b * T_SZ + q0 + rowA) * C_SZ + h * D_SZ + 2 * t;
    float* aoB = g_ao + (size_t)(b * T_SZ + q0 + rowB) * C_SZ + h * D_SZ + 2 * t;
    #pragma unroll
    for (int f = 0; f < 8; f++) {
        float2 vA, vB;
        vA.x = wmma::__float_to_tf32(oacc[f][0] * invA);
        vA.y = wmma::__float_to_tf32(oacc[f][1] * invA);
        vB.x = wmma::__float_to_tf32(oacc[f][2] * invB);
        vB.y = wmma::__float_to_tf32(oacc[f][3] * invB);
        *(float2*)(aoA + f * 8) = vA;
        *(float2*)(aoB + f * 8) = vB;
    }
}

// ---------------- launch ----------------
extern "C" void kernel_launch(void* const* d_in, const int* in_sizes, int n_in,
                              void* d_out, int out_size)
{
    const float* x    = (const float*)d_in[0];
    const float* Wqkv = (const float*)d_in[1];
    const float* bqkv = (const float*)d_in[2];
    const float* Wout = (const float*)d_in[3];
    const float* bout = (const float*)d_in[4];
    float* out = (float*)d_out;

    cudaFuncSetAttribute(gemm_tf32,
                         cudaFuncAttributeMaxDynamicSharedMemorySize, GEMM_SMEM_BYTES);
    cudaFuncSetAttribute(attn_kernel,
                         cudaFuncAttributeMaxDynamicSharedMemorySize, ATT_SMEM_BYTES);

    // prep: round all operands to tf32 in one launch
    round_all<<<(PREP_F4 + 255) / 256, 256>>>(
        (const float4*)x, (const float4*)Wqkv, (const float4*)Wout);

    // 1) QKV projection
    dim3 g1(3 * C_SZ / BN, M_SZ / BM);   // (24, 64)
    gemm_tf32<<<g1, 128, GEMM_SMEM_BYTES>>>(bqkv, nullptr, M_SZ, 3 * C_SZ, C_SZ, 0);

    // 2) causal flash attention
    dim3 g2(T_SZ / AQ, B_SZ * H_SZ);     // (16, 64)
    attn_kernel<<<g2, 256, ATT_SMEM_BYTES>>>();

    // 3) output projection
    dim3 g3(C_SZ / BN, M_SZ / BM);       // (8, 64)
    gemm_tf32<<<g3, 128, GEMM_SMEM_BYTES>>>(bout, out, M_SZ, C_SZ, C_SZ, 1);
}

// round 16
// speedup vs baseline: 1.1513x; 1.0043x over previous
#include <cuda_runtime.h>
#include <mma.h>
#include <math.h>
#include <stdint.h>

using namespace nvcuda;

#define B_SZ 4
#define T_SZ 2048
#define C_SZ 1024
#define H_SZ 16
#define D_SZ 64
#define M_SZ (B_SZ * T_SZ)   // 8192

// ---------------- scratch (static device globals; no allocation) ----------------
__device__ float g_q[(size_t)B_SZ * H_SZ * T_SZ * D_SZ];   // [B,H,T,D] tf32-rounded
__device__ float g_k[(size_t)B_SZ * H_SZ * T_SZ * D_SZ];
__device__ float g_v[(size_t)B_SZ * H_SZ * T_SZ * D_SZ];
__device__ float g_ao[(size_t)B_SZ * T_SZ * C_SZ];         // attention out, tf32-rounded
__device__ float g_xr[(size_t)M_SZ * C_SZ];                // x, tf32-rounded
__device__ float g_wqkv[(size_t)C_SZ * 3 * C_SZ];          // W_qkv, tf32-rounded
__device__ float g_wout[(size_t)C_SZ * C_SZ];              // W_out, tf32-rounded

// ---------------- cp.async helpers ----------------
__device__ __forceinline__ void cp_async16(void* smem, const void* gmem) {
    uint32_t s = (uint32_t)__cvta_generic_to_shared(smem);
    asm volatile("cp.async.cg.shared.global [%0], [%1], 16;\n" :: "r"(s), "l"(gmem));
}
__device__ __forceinline__ void cp_commit() {
    asm volatile("cp.async.commit_group;\n");
}
template<int N>
__device__ __forceinline__ void cp_wait() {
    asm volatile("cp.async.wait_group %0;\n" :: "n"(N));
}

// ---------------- raw tf32 mma (PTX-defined fragment layout) ----------------
__device__ __forceinline__ void mma_tf32(float* c, const uint32_t* a, const uint32_t* b) {
    asm volatile(
        "mma.sync.aligned.m16n8k8.row.col.f32.tf32.tf32.f32 "
        "{%0,%1,%2,%3}, {%4,%5,%6,%7}, {%8,%9}, {%0,%1,%2,%3};\n"
        : "+f"(c[0]), "+f"(c[1]), "+f"(c[2]), "+f"(c[3])
        : "r"(a[0]), "r"(a[1]), "r"(a[2]), "r"(a[3]), "r"(b[0]), "r"(b[1]));
}

// ---------------- prep: round all three operand arrays to tf32 (one launch) -----
#define XR_F4   (M_SZ * C_SZ / 4)            // 2,097,152
#define WQKV_F4 (3 * C_SZ * C_SZ / 4)        //   786,432
#define WOUT_F4 (C_SZ * C_SZ / 4)            //   262,144
#define PREP_F4 (XR_F4 + WQKV_F4 + WOUT_F4)  // 3,145,728

__global__ void round_all(const float4* __restrict__ x,
                          const float4* __restrict__ wqkv,
                          const float4* __restrict__ wout)
{
    int i = blockIdx.x * blockDim.x + threadIdx.x;
    if (i >= PREP_F4) return;
    const float4* src;
    float4* dst;
    if (i < XR_F4) {
        src = x + i;                     dst = (float4*)g_xr + i;
    } else if (i < XR_F4 + WQKV_F4) {
        int j = i - XR_F4;
        src = wqkv + j;                  dst = (float4*)g_wqkv + j;
    } else {
        int j = i - XR_F4 - WQKV_F4;
        src = wout + j;                  dst = (float4*)g_wout + j;
    }
    float4 v = *src;
    v.x = wmma::__float_to_tf32(v.x);
    v.y = wmma::__float_to_tf32(v.y);
    v.z = wmma::__float_to_tf32(v.z);
    v.w = wmma::__float_to_tf32(v.w);
    *dst = v;
}

// ---------------- GEMM v3c: raw m16n8k8, 128x128 CTA, GS=2, conflict-free B -----
// (unchanged from R15)
#define BM 128
#define BN 128
#define BK 32
#define GS 2
#define LDA (BK + 4)     // 36
#define LDB (BN + 8)     // 136
#define A_STG (BM * LDA)          // 4608 floats
#define B_STG (BK * LDB)          // 4352 floats
#define GEMM_SMEM_BYTES (GS * (A_STG + B_STG) * 4)   // 71680 B -> 3 CTAs/SM

__global__ void __launch_bounds__(128, 3) gemm_tf32(
    const float* __restrict__ bias, float* __restrict__ Cout,
    int M, int N, int K, int mode)
{
    extern __shared__ float gsm[];
    float* Ash = gsm;
    float* Bsh = gsm + GS * A_STG;

    const float* Aptr = (mode == 1) ? g_ao : g_xr;
    const float* Bm   = (mode == 1) ? g_wout : g_wqkv;

    int tid  = threadIdx.x;
    int warp = tid >> 5;
    int lane = tid & 31;
    int wm = warp >> 1;
    int wn = warp & 1;
    int g  = lane >> 2;
    int t  = lane & 3;
    int m0 = blockIdx.y * BM;
    int n0 = blockIdx.x * BN;

    float acc[4][8][4];
    #pragma unroll
    for (int i = 0; i < 4; i++)
        #pragma unroll
        for (int f = 0; f < 8; f++)
            #pragma unroll
            for (int e = 0; e < 4; e++) acc[i][f][e] = 0.f;

    int ar = tid >> 3,  ac = (tid & 7)  * 4;
    int br = tid >> 5,  bc = (tid & 31) * 4;

    auto load_tile = [&](int stage, int k0) {
        float* As = Ash + stage * A_STG;
        float* Bs = Bsh + stage * B_STG;
        #pragma unroll
        for (int i = 0; i < 8; i++) {
            int r = ar + i * 16;
            cp_async16(As + r * LDA + ac, Aptr + (size_t)(m0 + r) * K + k0 + ac);
        }
        #pragma unroll
        for (int i = 0; i < 8; i++) {
            int r = br + i * 4;
            cp_async16(Bs + r * LDB + bc, Bm + (size_t)(k0 + r) * N + n0 + bc);
        }
        cp_commit();
    };

    int KT = K / BK;
    load_tile(0, 0);

    for (int kt = 0; kt < KT; ++kt) {
        __syncthreads();
        if (kt + 1 < KT) {
            load_tile((kt + 1) & 1, (kt + 1) * BK);
            cp_wait<1>();
        } else {
            cp_wait<0>();
        }
        __syncthreads();

        float* As = Ash + (kt & 1) * A_STG;
        float* Bs = Bsh + (kt & 1) * B_STG;

        #pragma unroll
        for (int kk = 0; kk < BK; kk += 8) {
            uint32_t a[4][4];
            #pragma unroll
            for (int i = 0; i < 4; i++) {
                int rA = wm * 64 + i * 16 + g;
                a[i][0] = __float_as_uint(As[(rA    ) * LDA + kk + t]);
                a[i][1] = __float_as_uint(As[(rA + 8) * LDA + kk + t]);
                a[i][2] = __float_as_uint(As[(rA    ) * LDA + kk + t + 4]);
                a[i][3] = __float_as_uint(As[(rA + 8) * LDA + kk + t + 4]);
            }
            #pragma unroll
            for (int f = 0; f < 8; f++) {
                uint32_t bb[2];
                int nB = wn * 64 + f * 8 + g;
                bb[0] = __float_as_uint(Bs[(kk + t)     * LDB + nB]);
                bb[1] = __float_as_uint(Bs[(kk + t + 4) * LDB + nB]);
                #pragma unroll
                for (int i = 0; i < 4; i++)
                    mma_tf32(acc[i][f], a[i], bb);
            }
        }
    }
    __syncthreads();

    float* stg = Ash + warp * 1152;
    #pragma unroll
    for (int i = 0; i < 4; i++) {
        #pragma unroll
        for (int f = 0; f < 8; f++) {
            *(float2*)(stg + (g    ) * 68 + f * 8 + 2 * t) = make_float2(acc[i][f][0], acc[i][f][1]);
            *(float2*)(stg + (g + 8) * 68 + f * 8 + 2 * t) = make_float2(acc[i][f][2], acc[i][f][3]);
        }
        __syncwarp();
        #pragma unroll
        for (int e = 0; e < 8; e++) {
            int idx = lane + e * 32;
            int rr = idx >> 4, cc = (idx & 15) * 4;
            int m = m0 + wm * 64 + i * 16 + rr;
            int n = n0 + wn * 64 + cc;
            float4 v  = *(float4*)(stg + rr * 68 + cc);
            float4 bv = *(const float4*)(bias + n);
            v.x += bv.x; v.y += bv.y; v.z += bv.z; v.w += bv.w;
            if (mode == 0) {
                int third = n >> 10, c = n & 1023;
                int h = c >> 6, d = c & 63;
                int b = m >> 11, tt = m & 2047;
                float* dst = (third == 0) ? g_q : (third == 1) ? g_k : g_v;
                v.x = wmma::__float_to_tf32(v.x);
                v.y = wmma::__float_to_tf32(v.y);
                v.z = wmma::__float_to_tf32(v.z);
                v.w = wmma::__float_to_tf32(v.w);
                *(float4*)(dst + (((size_t)(b * H_SZ + h)) * T_SZ + tt) * D_SZ + d) = v;
            } else {
                *(float4*)(Cout + (size_t)m * N + n) = v;
            }
        }
        __syncwarp();
    }
}

// ---------------- Flash attention v5: Q-frags in registers, fused fk PV ----------
// Q fragments loaded once (loop-invariant); softmax+shfl+PV fused per fk so
// sacc registers die progressively (fits Q-hoist under the 128-reg cap).
#define AQ 128
#define AK 64
#define ALD 68            // Q/K pitch (bank 4g+t: conflict-free)
#define VLD 72            // V pitch (bank 8t+g: conflict-free)
#define K_STG (AK * ALD)                  // 4352 floats
#define V_STG (AK * VLD)                  // 4608 floats
#define ATT_SMEM_FLOATS (AQ * ALD + 2 * K_STG + 2 * V_STG)
#define ATT_SMEM_BYTES  (ATT_SMEM_FLOATS * 4)   // 106496 B -> 2 CTAs/SM

__global__ void __launch_bounds__(256, 2) attn_kernel()
{
    extern __shared__ float smbuf[];
    float* Qsh = smbuf;
    float* Ksh = Qsh + AQ * ALD;          // 2 stages
    float* Vsh = Ksh + 2 * K_STG;         // 2 stages

    int qt = gridDim.x - 1 - blockIdx.x;   // longest tiles first
    int q0 = qt * AQ;
    int bh = blockIdx.y;
    int b = bh >> 4, h = bh & 15;

    const float* Qb = g_q + (size_t)bh * T_SZ * D_SZ;
    const float* Kb = g_k + (size_t)bh * T_SZ * D_SZ;
    const float* Vb = g_v + (size_t)bh * T_SZ * D_SZ;

    int tid  = threadIdx.x;
    int warp = tid >> 5;
    int lane = tid & 31;
    int r0 = warp * 16;
    int g = lane >> 2;
    int t = lane & 3;
    int rowA = r0 + g, rowB = rowA + 8;
    int qiA = q0 + rowA, qiB = q0 + rowB;

    // load Q tile with 0.125 scale folded in
    #pragma unroll
    for (int i = 0; i < 8; i++) {
        int idx = tid + i * 256;
        int r = idx >> 4, c = (idx & 15) * 4;
        float4 v = *(const float4*)(Qb + (size_t)(q0 + r) * D_SZ + c);
        v.x *= 0.125f; v.y *= 0.125f; v.z *= 0.125f; v.w *= 0.125f;
        *(float4*)(Qsh + r * ALD + c) = v;
    }

    // K/V ring fill
    int kr = tid >> 4, kc = (tid & 15) * 4;
    auto fill_kv = [&](int stage, int k0) {
        float* Ks = Ksh + stage * K_STG;
        float* Vs = Vsh + stage * V_STG;
        #pragma unroll
        for (int i = 0; i < 4; i++) {
            int r = kr + i * 16;
            cp_async16(Ks + r * ALD + kc, Kb + (size_t)(k0 + r) * D_SZ + kc);
            cp_async16(Vs + r * VLD + kc, Vb + (size_t)(k0 + r) * D_SZ + kc);
        }
        cp_commit();
    };
    fill_kv(0, 0);

    // hoist Q fragments into registers (loop-invariant across K tiles)
    __syncthreads();
    uint32_t qa[8][4];
    #pragma unroll
    for (int k8 = 0; k8 < 8; k8++) {
        int kk = k8 * 8;
        qa[k8][0] = __float_as_uint(Qsh[rowA * ALD + kk + t]);
        qa[k8][1] = __float_as_uint(Qsh[rowB * ALD + kk + t]);
        qa[k8][2] = __float_as_uint(Qsh[rowA * ALD + kk + t + 4]);
        qa[k8][3] = __float_as_uint(Qsh[rowB * ALD + kk + t + 4]);
    }

    float oacc[8][4];
    #pragma unroll
    for (int f = 0; f < 8; f++)
        #pragma unroll
        for (int e = 0; e < 4; e++) oacc[f][e] = 0.f;

    float laccA = 0.f, laccB = 0.f;

    int nkt = 2 * qt + 2;
    int srcA = (lane & 0x1C) | (t >> 1);   // 4g + t/2
    int srcB = srcA + 2;
    bool odd = (t & 1);

    for (int kt = 0; kt < nkt; ++kt) {
        int k0 = kt * AK;
        __syncthreads();                      // all warps done reading stage (kt+1)&1
        if (kt + 1 < nkt) {
            fill_kv((kt + 1) & 1, k0 + AK);   // next tile flies during compute
            cp_wait<1>();                     // stage kt landed
        } else {
            cp_wait<0>();
        }
        __syncthreads();                      // stage kt visible

        float* Ks = Ksh + (kt & 1) * K_STG;
        float* Vs = Vsh + (kt & 1) * V_STG;

        // ---- S = (Q*0.125) @ K^T, Q from registers ----
        float sacc[8][4];
        #pragma unroll
        for (int f = 0; f < 8; f++)
            #pragma unroll
            for (int e = 0; e < 4; e++) sacc[f][e] = 0.f;

        #pragma unroll
        for (int k8 = 0; k8 < 8; k8++) {
            int kk = k8 * 8;
            #pragma unroll
            for (int f = 0; f < 8; f++) {
                uint32_t bb[2];
                bb[0] = __float_as_uint(Ks[(f * 8 + g) * ALD + kk + t]);
                bb[1] = __float_as_uint(Ks[(f * 8 + g) * ALD + kk + t + 4]);
                mma_tf32(sacc[f], qa[k8], bb);
            }
        }

        // ---- fused per-fk: softmax numerator -> shfl relayout -> PV mma ----
        #pragma unroll
        for (int fk = 0; fk < 8; fk++) {
            int c0 = k0 + fk * 8 + 2 * t;
            float p0 = (c0     <= qiA) ? __expf(fminf(sacc[fk][0], 60.f)) : 0.f;
            float p1 = (c0 + 1 <= qiA) ? __expf(fminf(sacc[fk][1], 60.f)) : 0.f;
            float p2 = (c0     <= qiB) ? __expf(fminf(sacc[fk][2], 60.f)) : 0.f;
            float p3 = (c0 + 1 <= qiB) ? __expf(fminf(sacc[fk][3], 60.f)) : 0.f;
            p0 = wmma::__float_to_tf32(p0);
            p1 = wmma::__float_to_tf32(p1);
            p2 = wmma::__float_to_tf32(p2);
            p3 = wmma::__float_to_tf32(p3);
            laccA += p0 + p1;
            laccB += p2 + p3;

            // C-frag -> A-frag relayout via quad shuffles (sacc[fk] dies here)
            float x0 = __shfl_sync(0xffffffffu, p0, srcA);
            float x1 = __shfl_sync(0xffffffffu, p1, srcA);
            float y0 = __shfl_sync(0xffffffffu, p2, srcA);
            float y1 = __shfl_sync(0xffffffffu, p3, srcA);
            float z0 = __shfl_sync(0xffffffffu, p0, srcB);
            float z1 = __shfl_sync(0xffffffffu, p1, srcB);
            float w0 = __shfl_sync(0xffffffffu, p2, srcB);
            float w1 = __shfl_sync(0xffffffffu, p3, srcB);
            uint32_t a[4];
            a[0] = __float_as_uint(odd ? x1 : x0);   // P[rowA][8fk + t]
            a[1] = __float_as_uint(odd ? y1 : y0);   // P[rowB][8fk + t]
            a[2] = __float_as_uint(odd ? z1 : z0);   // P[rowA][8fk + t+4]
            a[3] = __float_as_uint(odd ? w1 : w0);   // P[rowB][8fk + t+4]

            int kk = fk * 8;
            #pragma unroll
            for (int f = 0; f < 8; f++) {
                uint32_t bb[2];
                bb[0] = __float_as_uint(Vs[(kk + t)     * VLD + f * 8 + g]);
                bb[1] = __float_as_uint(Vs[(kk + t + 4) * VLD + f * 8 + g]);
                mma_tf32(oacc[f], a, bb);
            }
        }
    }

    // ---- row-sum reduction across the quad, normalize O, write directly ----
    laccA += __shfl_xor_sync(0xffffffffu, laccA, 1);
    laccA += __shfl_xor_sync(0xffffffffu, laccA, 2);
    laccB += __shfl_xor_sync(0xffffffffu, laccB, 1);
    laccB += __shfl_xor_sync(0xffffffffu, laccB, 2);
    float invA = 1.0f / laccA;
    float invB = 1.0f / laccB;

    float* aoA = g_ao + (size_t)(b * T_SZ + q0 + rowA) * C_SZ + h * D_SZ + 2 * t;
    float* aoB = g_ao + (size_t)(b * T_SZ + q0 + rowB) * C_SZ + h * D_SZ + 2 * t;
    #pragma unroll
    for (int f = 0; f < 8; f++) {
        float2 vA, vB;
        vA.x = wmma::__float_to_tf32(oacc[f][0] * invA);
        vA.y = wmma::__float_to_tf32(oacc[f][1] * invA);
        vB.x = wmma::__float_to_tf32(oacc[f][2] * invB);
        vB.y = wmma::__float_to_tf32(oacc[f][3] * invB);
        *(float2*)(aoA + f * 8) = vA;
        *(float2*)(aoB + f * 8) = vB;
    }
}

// ---------------- launch ----------------
extern "C" void kernel_launch(void* const* d_in, const int* in_sizes, int n_in,
                              void* d_out, int out_size)
{
    const float* x    = (const float*)d_in[0];
    const float* Wqkv = (const float*)d_in[1];
    const float* bqkv = (const float*)d_in[2];
    const float* Wout = (const float*)d_in[3];
    const float* bout = (const float*)d_in[4];
    float* out = (float*)d_out;

    cudaFuncSetAttribute(gemm_tf32,
                         cudaFuncAttributeMaxDynamicSharedMemorySize, GEMM_SMEM_BYTES);
    cudaFuncSetAttribute(attn_kernel,
                         cudaFuncAttributeMaxDynamicSharedMemorySize, ATT_SMEM_BYTES);

    // prep: round all operands to tf32 in one launch
    round_all<<<(PREP_F4 + 255) / 256, 256>>>(
        (const float4*)x, (const float4*)Wqkv, (const float4*)Wout);

    // 1) QKV projection
    dim3 g1(3 * C_SZ / BN, M_SZ / BM);   // (24, 64)
    gemm_tf32<<<g1, 128, GEMM_SMEM_BYTES>>>(bqkv, nullptr, M_SZ, 3 * C_SZ, C_SZ, 0);

    // 2) causal flash attention
    dim3 g2(T_SZ / AQ, B_SZ * H_SZ);     // (16, 64)
    attn_kernel<<<g2, 256, ATT_SMEM_BYTES>>>();

    // 3) output projection
    dim3 g3(C_SZ / BN, M_SZ / BM);       // (8, 64)
    gemm_tf32<<<g3, 128, GEMM_SMEM_BYTES>>>(bout, out, M_SZ, C_SZ, C_SZ, 1);
}